// round 17
// baseline (speedup 1.0000x reference)
#include <cuda_runtime.h>
#include <cuda_bf16.h>
#include <cuda_fp16.h>
#include <cstdint>

#define B_ 2
#define H_ 16
#define S_ 2048
#define DKK 64
#define TQ 128
#define TKEY 128
#define NKT 16
#define NTH 256
#define PITCH 144

// Q pre-scaled by 0.125*log2(e): softmax exp becomes bare ex2.approx
#define QSCALE 0.18033688011112042f

// SMEM: Q, K, V fp16 tiles + single-tile mask bitmap (2KB)
#define SM_Q   0
#define SM_K   18432
#define SM_V   36864
#define SM_MSK 55296
#define SM_TOTAL (55296 + 2048)

// unnormalized P scratch, packed fp16 pairs.
// layout [strip][kt][wid][j][lane]:
//   strip stride = 16*8*16*32 = 65536
//   kt stride    =    8*16*32 =  4096
//   wid stride   =      16*32 =   512
//   j stride     =         32
__device__ uint2 g_p[(size_t)512 * 16 * 8 * 16 * 32];

__device__ __forceinline__ uint32_t smem_u32(const void* p) {
    uint32_t a;
    asm("{ .reg .u64 t; cvta.to.shared.u64 t, %1; cvt.u32.u64 %0, t; }" : "=r"(a) : "l"(p));
    return a;
}
__device__ __forceinline__ float ex2f(float x) {
    float y;
    asm("ex2.approx.f32 %0, %1;" : "=f"(y) : "f"(x));
    return y;
}
__device__ __forceinline__ void ldsm_x4(uint32_t addr, uint32_t r[4]) {
    asm volatile("ldmatrix.sync.aligned.m8n8.x4.shared.b16 {%0,%1,%2,%3}, [%4];"
        : "=r"(r[0]), "=r"(r[1]), "=r"(r[2]), "=r"(r[3]) : "r"(addr));
}
__device__ __forceinline__ void ldsm_x4t(uint32_t addr, uint32_t r[4]) {
    asm volatile("ldmatrix.sync.aligned.m8n8.x4.trans.shared.b16 {%0,%1,%2,%3}, [%4];"
        : "=r"(r[0]), "=r"(r[1]), "=r"(r[2]), "=r"(r[3]) : "r"(addr));
}
__device__ __forceinline__ void mma_f16(float c[4], const uint32_t a[4], uint32_t b0, uint32_t b1) {
    asm volatile("mma.sync.aligned.m16n8k16.row.col.f32.f16.f16.f32 "
        "{%0,%1,%2,%3},{%4,%5,%6,%7},{%8,%9},{%0,%1,%2,%3};"
        : "+f"(c[0]), "+f"(c[1]), "+f"(c[2]), "+f"(c[3])
        : "r"(a[0]), "r"(a[1]), "r"(a[2]), "r"(a[3]), "r"(b0), "r"(b1));
}
__device__ __forceinline__ uint32_t pack_h2(float a, float b) {
    __half2 h = __floats2half2_rn(a, b);
    return *(uint32_t*)&h;
}
__device__ __forceinline__ void load_half(const float4* __restrict__ g4, char* smem,
                                          int oh, int tid) {
    #pragma unroll
    for (int i = 0; i < 8; i++) {
        int idx4 = tid + i * NTH;
        float4 v = g4[idx4];
        int row = idx4 >> 4;
        int d0  = (idx4 & 15) * 4;
        int off = row * PITCH + d0 * 2;
        *(uint2*)(smem + oh + off) = make_uint2(pack_h2(v.x, v.y), pack_h2(v.z, v.w));
    }
}
__device__ __forceinline__ void load_half_scaled(const float4* __restrict__ g4, char* smem,
                                                 int oh, int tid, float sc) {
    #pragma unroll
    for (int i = 0; i < 8; i++) {
        int idx4 = tid + i * NTH;
        float4 v = g4[idx4];
        int row = idx4 >> 4;
        int d0  = (idx4 & 15) * 4;
        int off = row * PITCH + d0 * 2;
        *(uint2*)(smem + oh + off) =
            make_uint2(pack_h2(v.x * sc, v.y * sc), pack_h2(v.z * sc, v.w * sc));
    }
}

extern "C" __global__ void __launch_bounds__(NTH, 2)
attn_mma_kernel(const float* __restrict__ Q, const float* __restrict__ K,
                const float* __restrict__ V, const int* __restrict__ mask,
                float* __restrict__ ctx_out, float* __restrict__ scores_out)
{
    extern __shared__ char smem[];
    const uint32_t sb = smem_u32(smem);
    const int tid  = threadIdx.x;
    const int wid  = tid >> 5;
    const int lane = tid & 31;
    const int g    = lane >> 2;
    const int q    = lane & 3;

    const int bh = blockIdx.y;
    const int qt = blockIdx.x;
    const int q0 = qt * TQ;
    const int strip = bh * (S_ / TQ) + qt;
    const size_t row0      = (size_t)bh * S_ + q0 + 16 * wid + g;
    const size_t kvbase    = (size_t)bh * S_ * DKK;
    const size_t mrow_base = ((size_t)bh * S_ + q0) * S_;
    // [strip][kt][wid][j][lane]; this thread's (strip, wid, lane) base
    uint2* pbase = g_p + (size_t)strip * 65536 + (size_t)wid * 512 + lane;

    load_half_scaled((const float4*)(Q + ((size_t)bh * S_ + q0) * DKK), smem, SM_Q, tid, QSCALE);
    __syncthreads();

    uint32_t qh[4][4];
    {
        const uint32_t qrow = (uint32_t)(16 * wid + (lane & 15)) * PITCH + ((lane >> 4) & 1) * 16;
        #pragma unroll
        for (int s = 0; s < 4; s++)
            ldsm_x4(sb + SM_Q + qrow + 32 * s, qh[s]);
    }

    const uint32_t kAddr4 = (uint32_t)(lane & 7) * PITCH + ((lane >> 3) & 3) * 16;
    const uint32_t vAddr4 = (uint32_t)(lane & 15) * PITCH + ((lane >> 4) & 1) * 16;
    const int bmRow0 = (16 * wid + g) * 16;
    const int bmRow1 = (16 * wid + g + 8) * 16;

    // ================= PASS 1: rowsums + P scratch =================
    float rsum0 = 0.0f, rsum1 = 0.0f;
    for (int kt = 0; kt < NKT; kt++) {
        __syncthreads();
        load_half((const float4*)(K + kvbase + (size_t)kt * TKEY * DKK), smem, SM_K, tid);

        // coalesced mask tile -> 2KB bitmap (single buffer, reused per tile)
        #pragma unroll
        for (int i = 0; i < 8; i++) {
            int chunk = tid + i * NTH;
            int mr = chunk >> 4;
            int mb = chunk & 15;
            const int* mp = mask + mrow_base + (size_t)mr * S_ + kt * TKEY + 8 * mb;
            int4 a = __ldcs((const int4*)mp);
            int4 b = __ldcs((const int4*)(mp + 4));
            unsigned char byte =
                (a.x ? 1u : 0u) | (a.y ? 2u : 0u) | (a.z ? 4u : 0u) | (a.w ? 8u : 0u) |
                (b.x ? 16u : 0u) | (b.y ? 32u : 0u) | (b.z ? 64u : 0u) | (b.w ? 128u : 0u);
            smem[SM_MSK + mr * 16 + mb] = (char)byte;
        }
        __syncthreads();

        uint4 t0 = *(const uint4*)(smem + SM_MSK + bmRow0);
        uint4 t1 = *(const uint4*)(smem + SM_MSK + bmRow1);
        const uint32_t bm0[4] = {t0.x, t0.y, t0.z, t0.w};
        const uint32_t bm1[4] = {t1.x, t1.y, t1.z, t1.w};

        uint2* ptile = pbase + (size_t)kt * 4096;     // kt stride = 8*16*32
        #pragma unroll
        for (int j = 0; j < 16; j++) {
            float c[4] = {0.f, 0.f, 0.f, 0.f};
            uint32_t kh[4], kh2[4];
            uint32_t base = (uint32_t)(8 * j) * PITCH + kAddr4;
            ldsm_x4(sb + SM_K + base,      kh);
            ldsm_x4(sb + SM_K + base + 64, kh2);
            mma_f16(c, qh[0], kh[0],  kh[1]);
            mma_f16(c, qh[1], kh[2],  kh[3]);
            mma_f16(c, qh[2], kh2[0], kh2[1]);
            mma_f16(c, qh[3], kh2[2], kh2[3]);

            uint32_t bit0 = (bm0[j >> 2] >> ((j & 3) * 8 + 2 * q)) & 3u;
            uint32_t bit1 = (bm1[j >> 2] >> ((j & 3) * 8 + 2 * q)) & 3u;
            float p0 = (bit0 & 1u) ? 0.0f : ex2f(c[0]);
            float p1 = (bit0 & 2u) ? 0.0f : ex2f(c[1]);
            float p2 = (bit1 & 1u) ? 0.0f : ex2f(c[2]);
            float p3 = (bit1 & 2u) ? 0.0f : ex2f(c[3]);
            rsum0 += p0 + p1;
            rsum1 += p2 + p3;
            ptile[j * 32] = make_uint2(pack_h2(p0, p1), pack_h2(p2, p3));
        }
    }

    #pragma unroll
    for (int o = 1; o < 4; o <<= 1) {
        rsum0 += __shfl_xor_sync(0xffffffffu, rsum0, o);
        rsum1 += __shfl_xor_sync(0xffffffffu, rsum1, o);
    }
    const float inv0 = 1.0f / rsum0;
    const float inv1 = 1.0f / rsum1;

    // ================= PASS 2: scores from scratch + PV =================
    float cacc[8][4];
    #pragma unroll
    for (int n = 0; n < 8; n++)
        #pragma unroll
        for (int e = 0; e < 4; e++) cacc[n][e] = 0.0f;

    for (int kt = 0; kt < NKT; kt++) {
        __syncthreads();
        load_half((const float4*)(V + kvbase + (size_t)kt * TKEY * DKK), smem, SM_V, tid);
        __syncthreads();

        uint2* ptile = pbase + (size_t)kt * 4096;
        uint32_t ah[4];

        #pragma unroll
        for (int j = 0; j < 16; j++) {
            uint2 pv = ptile[j * 32];
            // scores: unpack, normalize, write
            float2 f01 = __half22float2(*(__half2*)&pv.x);
            float2 f23 = __half22float2(*(__half2*)&pv.y);
            const int col = kt * TKEY + 8 * j + 2 * q;
            *(float2*)(scores_out + row0 * S_ + col)       = make_float2(f01.x * inv0, f01.y * inv0);
            *(float2*)(scores_out + (row0 + 8) * S_ + col) = make_float2(f23.x * inv1, f23.y * inv1);
            // PV A-fragments (unnormalized; ctx normalized at the end)
            const int o = (j & 1) * 2;
            ah[o]     = pv.x;
            ah[o + 1] = pv.y;

            if (j & 1) {
                const int s = j >> 1;
                #pragma unroll
                for (int np = 0; np < 4; np++) {
                    uint32_t addr = (uint32_t)(16 * s) * PITCH + 32 * np + vAddr4;
                    uint32_t vh[4];
                    ldsm_x4t(sb + SM_V + addr, vh);
                    mma_f16(cacc[2 * np],     ah, vh[0], vh[1]);
                    mma_f16(cacc[2 * np + 1], ah, vh[2], vh[3]);
                }
            }
        }
    }

    #pragma unroll
    for (int n = 0; n < 8; n++) {
        *(float2*)(ctx_out + row0 * DKK + 8 * n + 2 * q) =
            make_float2(cacc[n][0] * inv0, cacc[n][1] * inv0);
        *(float2*)(ctx_out + (row0 + 8) * DKK + 8 * n + 2 * q) =
            make_float2(cacc[n][2] * inv1, cacc[n][3] * inv1);
    }
}

extern "C" void kernel_launch(void* const* d_in, const int* in_sizes, int n_in,
                              void* d_out, int out_size) {
    const float* Q = (const float*)d_in[0];
    const float* K = (const float*)d_in[1];
    const float* V = (const float*)d_in[2];
    const int* mask = (const int*)d_in[3];

    float* ctx    = (float*)d_out;
    float* scores = (float*)d_out + (long long)B_ * H_ * S_ * DKK;

    cudaFuncSetAttribute(attn_mma_kernel, cudaFuncAttributeMaxDynamicSharedMemorySize, SM_TOTAL);

    dim3 grid(S_ / TQ, B_ * H_);   // (16, 32)
    attn_mma_kernel<<<grid, NTH, SM_TOTAL>>>(Q, K, V, mask, ctx, scores);
}